// round 5
// baseline (speedup 1.0000x reference)
#include <cuda_runtime.h>
#include <math.h>

// ---------------------------------------------------------------------------
// AdaptiveFeaturePropagation: upsample -> conv_reduce(x2) -> conv2 -> conv3
//                             -> softmax -> spatially-variant 7x7 conv
// All fp32. Scratch in __device__ globals (no allocation).
// ---------------------------------------------------------------------------

static constexpr int HH = 129;
static constexpr int WW = 129;
static constexpr int HWP = HH * WW;      // 16641

// slot = 2*b + frame  (frame 0 = cur, 1 = key) -> matches concat layout
__device__ float g_up  [4 * 128 * HWP];  // upsampled low features, 4 images
__device__ float g_red [2 * 512 * HWP];  // relu(conv_reduce(cur)) ++ relu(conv_reduce(key)) per batch
__device__ float g_c2  [2 * 256 * HWP];  // relu(conv2)
__device__ float g_kern[2 * 49  * HWP];  // softmax(relu(conv3))

// ---------------------------------------------------------------------------
// 1) Bilinear upsample (half-pixel centers, = torch align_corners=False /
//    jax.image.resize "bilinear" for upsampling)
// ---------------------------------------------------------------------------
__global__ __launch_bounds__(256)
void upsample_kernel(const float* __restrict__ cur, const float* __restrict__ key)
{
    int idx = blockIdx.x * 256 + threadIdx.x;
    if (idx >= 4 * 128 * HWP) return;
    int slot = idx / (128 * HWP);
    int rem  = idx - slot * (128 * HWP);
    int c    = rem / HWP;
    int p    = rem - c * HWP;
    int Y = p / WW, X = p - Y * WW;
    int frame = slot & 1, b = slot >> 1;
    const float* src = (frame ? key : cur) + (b * 128 + c) * (33 * 33);

    const float s = 33.0f / 129.0f;
    float fy = (Y + 0.5f) * s - 0.5f;
    float fx = (X + 0.5f) * s - 0.5f;
    float y0f = floorf(fy), x0f = floorf(fx);
    float wy = fy - y0f, wx = fx - x0f;
    int y0 = (int)y0f, x0 = (int)x0f;
    int y0c = max(y0, 0), y1c = min(y0 + 1, 32);
    int x0c = max(x0, 0), x1c = min(x0 + 1, 32);

    float v00 = src[y0c * 33 + x0c], v01 = src[y0c * 33 + x1c];
    float v10 = src[y1c * 33 + x0c], v11 = src[y1c * 33 + x1c];
    float v0 = v00 + (v01 - v00) * wx;
    float v1 = v10 + (v11 - v10) * wx;
    g_up[idx] = v0 + (v1 - v0) * wy;
}

// ---------------------------------------------------------------------------
// 2/3) 3x3 conv as implicit GEMM.  M = HWP pixels, N = OC (256), K = CIN*9.
//      Block tile 128(M) x 64(N), BK=8, 256 threads, 8x4 register tile with
//      stride-16 fragment mapping (coalesced 64B stores per channel).
//      MODE 0: g_up(128ch, 4 imgs)  -> g_red(256ch slots)   [conv_reduce]
//      MODE 1: g_red(512ch, 2 imgs) -> g_c2(256ch)          [conv2]
//      ReLU fused into epilogue.
// ---------------------------------------------------------------------------
template<int CIN, int MODE>
__global__ __launch_bounds__(256)
void conv_igemm(const float* __restrict__ w, const float* __restrict__ bias)
{
    constexpr int Kdim = CIN * 9;
    __shared__ float As[8][128];
    __shared__ float Bs[8][64];

    const int m0 = blockIdx.x * 128;
    const int n0 = blockIdx.y * 64;

    const float* inImg;
    float* outImg;
    if (MODE == 0) {
        inImg  = g_up  + blockIdx.z * (128 * HWP);
        outImg = g_red + blockIdx.z * (256 * HWP);
    } else {
        inImg  = g_red + blockIdx.z * (512 * HWP);
        outImg = g_c2  + blockIdx.z * (256 * HWP);
    }

    const int tid  = threadIdx.x;
    const int tcol = tid & 15;   // m-dimension lane (16)
    const int trow = tid >> 4;   // n-dimension lane (16)

    float acc[8][4];
#pragma unroll
    for (int i = 0; i < 8; i++)
#pragma unroll
        for (int j = 0; j < 4; j++) acc[i][j] = 0.f;

    for (int k0 = 0; k0 < Kdim; k0 += 8) {
        // --- load A tile (128 x 8, im2col on the fly) ---
#pragma unroll
        for (int r = 0; r < 4; r++) {
            int e  = tid + r * 256;
            int kl = e >> 7, ml = e & 127;
            int m  = m0 + ml;
            int k  = k0 + kl;
            float v = 0.f;
            if (m < HWP) {
                int ci = k / 9;
                int t  = k - ci * 9;
                int ky = t / 3;
                int kx = t - ky * 3;
                int yy = m / WW;
                int xx = m - yy * WW;
                yy += ky - 1;
                xx += kx - 1;
                if ((unsigned)yy < (unsigned)HH && (unsigned)xx < (unsigned)WW)
                    v = __ldg(inImg + ci * HWP + yy * WW + xx);
            }
            As[kl][ml] = v;
        }
        // --- load B tile (8 x 64): w is [OC][CIN][3][3] => B[k][n] = w[n*Kdim + k] ---
#pragma unroll
        for (int r = 0; r < 2; r++) {
            int e  = tid + r * 256;
            int kl = e >> 6, nl = e & 63;
            Bs[kl][nl] = __ldg(w + (n0 + nl) * Kdim + k0 + kl);
        }
        __syncthreads();

#pragma unroll
        for (int kk = 0; kk < 8; kk++) {
            float a[8], bb[4];
#pragma unroll
            for (int i = 0; i < 8; i++) a[i] = As[kk][tcol + i * 16];
#pragma unroll
            for (int j = 0; j < 4; j++) bb[j] = Bs[kk][trow + j * 16];
#pragma unroll
            for (int i = 0; i < 8; i++)
#pragma unroll
                for (int j = 0; j < 4; j++)
                    acc[i][j] += a[i] * bb[j];
        }
        __syncthreads();
    }

    // epilogue: bias + relu, coalesced (16 consecutive pixels per (trow,j,i))
#pragma unroll
    for (int j = 0; j < 4; j++) {
        int n = n0 + trow + j * 16;
        float bv = bias[n];
#pragma unroll
        for (int i = 0; i < 8; i++) {
            int m = m0 + tcol + i * 16;
            if (m < HWP)
                outImg[n * HWP + m] = fmaxf(acc[i][j] + bv, 0.f);
        }
    }
}

// ---------------------------------------------------------------------------
// 4) conv3 (1x1, 256->49) + bias + relu + softmax over the 49 channels.
//    One thread per pixel, 49 register accumulators, weights staged in smem
//    in two 128-channel halves (25 KB each pass).
// ---------------------------------------------------------------------------
__global__ __launch_bounds__(256)
void conv3_softmax_kernel(const float* __restrict__ w3, const float* __restrict__ b3)
{
    __shared__ float sw[49 * 128];
    int g = blockIdx.x * 256 + threadIdx.x;
    bool valid = g < 2 * HWP;
    int b = 0, p = 0;
    if (valid) { b = g / HWP; p = g - b * HWP; }

    float acc[49];
#pragma unroll
    for (int t = 0; t < 49; t++) acc[t] = 0.f;

    for (int h = 0; h < 2; h++) {
        __syncthreads();
        for (int e = threadIdx.x; e < 49 * 128; e += 256)
            sw[e] = w3[(e >> 7) * 256 + h * 128 + (e & 127)];
        __syncthreads();
        if (valid) {
            const float* xc = g_c2 + b * (256 * HWP) + h * 128 * HWP + p;
            for (int cl = 0; cl < 128; cl++) {
                float xv = __ldg(xc + cl * HWP);
#pragma unroll
                for (int t = 0; t < 49; t++)
                    acc[t] += xv * sw[t * 128 + cl];
            }
        }
    }
    if (!valid) return;

    float mx = -1e30f;
#pragma unroll
    for (int t = 0; t < 49; t++) {
        acc[t] = fmaxf(acc[t] + b3[t], 0.f);   // relu before softmax
        mx = fmaxf(mx, acc[t]);
    }
    float s = 0.f;
#pragma unroll
    for (int t = 0; t < 49; t++) { acc[t] = expf(acc[t] - mx); s += acc[t]; }
    float inv = 1.f / s;
#pragma unroll
    for (int t = 0; t < 49; t++)
        g_kern[(b * 49 + t) * HWP + p] = acc[t] * inv;
}

// ---------------------------------------------------------------------------
// 5) Spatially-variant 7x7 conv:
//    out[b,c,y,x] = sum_{i,j} kern[b,i,j,y,x] * feat[b,c,y+i-3,x+j-3]
//    Block = 8x16 spatial tile; 49 kernel planes for the tile cached in smem;
//    256 threads = 2 channels x 128 pixels; feature taps via L1 (__ldg).
// ---------------------------------------------------------------------------
__global__ __launch_bounds__(256)
void svc_kernel(const float* __restrict__ feat, float* __restrict__ out)
{
    __shared__ float sk[49][128];
    const int x0 = blockIdx.x * 16, y0 = blockIdx.y * 8, b = blockIdx.z;
    const int tid = threadIdx.x;

    for (int e = tid; e < 49 * 128; e += 256) {
        int t = e >> 7, pix = e & 127;
        int yy = y0 + (pix >> 4), xx = x0 + (pix & 15);
        float v = 0.f;
        if (yy < HH && xx < WW) v = g_kern[(b * 49 + t) * HWP + yy * WW + xx];
        sk[t][pix] = v;
    }
    __syncthreads();

    const int half = tid >> 7;       // channel interleave
    const int pix  = tid & 127;
    const int y = y0 + (pix >> 4);
    const int x = x0 + (pix & 15);
    const bool valid = (y < HH) && (x < WW);
    const float* fb = feat + b * 256 * HWP;

    for (int c = half; c < 256; c += 2) {
        const float* fc = fb + c * HWP;
        float acc = 0.f;
#pragma unroll
        for (int i = 0; i < 7; i++) {
            int yy = y + i - 3;
            if ((unsigned)yy < (unsigned)HH) {
#pragma unroll
                for (int j = 0; j < 7; j++) {
                    int xx = x + j - 3;
                    if ((unsigned)xx < (unsigned)WW)
                        acc += sk[i * 7 + j][pix] * __ldg(fc + yy * WW + xx);
                }
            }
        }
        if (valid) out[(b * 256 + c) * HWP + y * WW + x] = acc;
    }
}

// ---------------------------------------------------------------------------
// Launcher (graph-capturable: plain kernel launches only)
// Inputs (metadata order):
//  0 current_frame_low_features (2,128,33,33)
//  1 key_frame_low_features     (2,128,33,33)
//  2 key_frame_high_features    (2,256,129,129)
//  3 w_reduce (256,128,3,3)  4 b_reduce (256)
//  5 w_conv2  (256,512,3,3)  6 b_conv2  (256)
//  7 w_conv3  (49,256,1,1)   8 b_conv3  (49)
// Output: (2,256,129,129) float32
// ---------------------------------------------------------------------------
extern "C" void kernel_launch(void* const* d_in, const int* in_sizes, int n_in,
                              void* d_out, int out_size)
{
    const float* cur = (const float*)d_in[0];
    const float* key = (const float*)d_in[1];
    const float* hi  = (const float*)d_in[2];
    const float* w1  = (const float*)d_in[3];
    const float* b1  = (const float*)d_in[4];
    const float* w2  = (const float*)d_in[5];
    const float* b2  = (const float*)d_in[6];
    const float* w3  = (const float*)d_in[7];
    const float* b3  = (const float*)d_in[8];
    float* out = (float*)d_out;

    // 1) upsample both low-feature tensors into g_up (4 image slots)
    upsample_kernel<<<(4 * 128 * HWP + 255) / 256, 256>>>(cur, key);

    // 2) conv_reduce (128->256) for all 4 images, relu, into concat layout g_red
    conv_igemm<128, 0><<<dim3(131, 4, 4), 256>>>(w1, b1);

    // 3) conv2 (512->256) per batch, relu, into g_c2
    conv_igemm<512, 1><<<dim3(131, 4, 2), 256>>>(w2, b2);

    // 4) conv3 + relu + softmax -> g_kern
    conv3_softmax_kernel<<<(2 * HWP + 255) / 256, 256>>>(w3, b3);

    // 5) spatially-variant conv -> final output
    svc_kernel<<<dim3(9, 17, 2), 256>>>(hi, out);
}